// round 2
// baseline (speedup 1.0000x reference)
#include <cuda_runtime.h>

// db4 dec_lo coefficients
#define G0 (-0.010597401784997278f)
#define G1 ( 0.032883011666982945f)
#define G2 ( 0.030841381835986965f)
#define G3 (-0.18703481171888114f)
#define G4 (-0.02798376941698385f)
#define G5 ( 0.6308807679295904f)
#define G6 ( 0.7148465705525415f)
#define G7 ( 0.23037781330885523f)

// Problem shape: x is [16, 512, 4096] fp32; rows = 16*512 = 8192, L = 4096.
// ca length = (L + 7) / 2 = 2051.
#define ROW_L 4096
#define CA_LEN 2051

// Shared layout:
//   sx[i + 8] = x_sym[i] for i in [-6, 4102)   (offset 8 keeps float4 alignment)
//   sca[k]    = analysis (approx) coefficients, k in [0, 2051)
__global__ __launch_bounds__(256) void db4_lowhigh_kernel(
    const float* __restrict__ x,
    float* __restrict__ low,
    float* __restrict__ high)
{
    __shared__ float sx[ROW_L + 16];   // 4112 floats
    __shared__ float sca[CA_LEN + 1];  // 2052 floats

    const int t = threadIdx.x;
    const size_t row = blockIdx.x;
    const float* __restrict__ xr = x + row * (size_t)ROW_L;

    // --- Phase 1: load row into shared (float4, fully coalesced) + halos ---
    const float4* __restrict__ x4 = (const float4*)xr;
    float4* s4 = (float4*)sx;
#pragma unroll
    for (int ii = 0; ii < 4; ii++) {
        s4[t + ii * 256 + 2] = x4[t + ii * 256];   // sx element offset 8 = float4 idx 2
    }
    if (t < 6) {
        // left halo: x_sym[t-6] = x[5 - t]   -> sx[(t-6)+8] = sx[t+2]
        sx[t + 2] = xr[5 - t];
        // right halo: x_sym[4096+t] = x[4095 - t] -> sx[4104 + t]
        sx[4104 + t] = xr[4095 - t];
    }
    __syncthreads();

    // --- Phase 2: analysis coeffs  ca[k] = sum_s x_sym[2k+1-s]*g[s] ---
    // x_sym[2k+1-s] = sx[2k+9-s]; with p = sx + 2k + 2, that's p[7-s].
#pragma unroll
    for (int jj = 0; jj < 9; jj++) {
        int k = t + jj * 256;
        if (k < CA_LEN) {
            const float* p = sx + 2 * k + 2;
            float a;
            a  = p[7] * G0;
            a += p[6] * G1;
            a += p[5] * G2;
            a += p[4] * G3;
            a += p[3] * G4;
            a += p[2] * G5;
            a += p[1] * G6;
            a += p[0] * G7;
            sca[k] = a;
        }
    }
    __syncthreads();

    // --- Phase 3: synthesis + residual, float4 stores ---
    // even n: low[n] = sum_j ca[n/2 + j]     * g[2j+1]
    // odd  n: low[n] = sum_j ca[(n-1)/2 + j] * g[2j]
    float* __restrict__ lo = low + row * (size_t)ROW_L;
    float* __restrict__ hi = high + row * (size_t)ROW_L;
#pragma unroll
    for (int ii = 0; ii < 4; ii++) {
        int i = t + ii * 256;      // float4 index; covers n = 4i .. 4i+3
        int m = 2 * i;
        float c0 = sca[m];
        float c1 = sca[m + 1];
        float c2 = sca[m + 2];
        float c3 = sca[m + 3];
        float c4 = sca[m + 4];

        float l0 = c0 * G1 + c1 * G3 + c2 * G5 + c3 * G7;  // n = 4i   (even, base 2i)
        float l1 = c0 * G0 + c1 * G2 + c2 * G4 + c3 * G6;  // n = 4i+1 (odd,  base 2i)
        float l2 = c1 * G1 + c2 * G3 + c3 * G5 + c4 * G7;  // n = 4i+2 (even, base 2i+1)
        float l3 = c1 * G0 + c2 * G2 + c3 * G4 + c4 * G6;  // n = 4i+3 (odd,  base 2i+1)

        float4 xv = s4[i + 2];
        ((float4*)lo)[i] = make_float4(l0, l1, l2, l3);
        ((float4*)hi)[i] = make_float4(xv.x - l0, xv.y - l1, xv.z - l2, xv.w - l3);
    }
}

extern "C" void kernel_launch(void* const* d_in, const int* in_sizes, int n_in,
                              void* d_out, int out_size)
{
    const float* x = (const float*)d_in[0];
    const int n = in_sizes[0];              // total elements = B*C*L
    const int rows = n / ROW_L;             // 8192
    float* low = (float*)d_out;             // output tuple order: (low_freq, high_freq)
    float* high = (float*)d_out + (size_t)n;

    db4_lowhigh_kernel<<<rows, 256>>>(x, low, high);
}

// round 7
// speedup vs baseline: 1.0879x; 1.0879x over previous
#include <cuda_runtime.h>

// db4 dec_lo coefficients
static constexpr float Gf[8] = {
    -0.010597401784997278f,  0.032883011666982945f,
     0.030841381835986965f, -0.18703481171888114f,
    -0.02798376941698385f,   0.6308807679295904f,
     0.7148465705525415f,    0.23037781330885523f };

// Composed analysis+synthesis filters (details zeroed):
//   low[2q]   = sum_{d=-6..7} Ecoef(d) * x_sym[2q+d]
//   low[2q+1] = sum_{d=-6..7} Ocoef(d) * x_sym[2q+d]
// derived from ca[k] = sum_s x_sym[2k+1-s] g[s] and
//   low[2q]   = sum_j ca[q+j] g[2j+1]
//   low[2q+1] = sum_j ca[q+j] g[2j]
__host__ __device__ static constexpr float Ecoef(int d) {
    float r = 0.f;
    for (int j = 0; j < 4; j++) {
        int s = 2 * j + 1 - d;
        if (s >= 0 && s < 8) r += Gf[2 * j + 1] * Gf[s];
    }
    return r;
}
__host__ __device__ static constexpr float Ocoef(int d) {
    float r = 0.f;
    for (int j = 0; j < 4; j++) {
        int s = 2 * j + 1 - d;
        if (s >= 0 && s < 8) r += Gf[2 * j] * Gf[s];
    }
    return r;
}

#define ROW_L 4096

// sx[m] = x_sym[m - 8], m in [0, 4112): symmetric extension baked into halo.
__global__ __launch_bounds__(256) void db4_fused_kernel(
    const float* __restrict__ x,
    float* __restrict__ low,
    float* __restrict__ high)
{
    __shared__ float sx[ROW_L + 16];   // 4112 floats = 16.4 KB

    const int t = threadIdx.x;
    const size_t row = blockIdx.x;
    const float* __restrict__ xr = x + row * (size_t)ROW_L;

    // --- load row into shared (float4, coalesced, conflict-free) + halos ---
    const float4* __restrict__ x4 = (const float4*)xr;
    float4* s4 = (float4*)sx;
#pragma unroll
    for (int ii = 0; ii < 4; ii++) {
        s4[t + ii * 256 + 2] = x4[t + ii * 256];   // sx[m]=x[m-8] for m=8..4103
    }
    if (t < 8) {
        sx[t] = xr[7 - t];            // x_sym[t-8] = x[7-t]  (left symmetric ext)
        sx[4104 + t] = xr[4095 - t];  // x_sym[4096+t] = x[4095-t] (right ext)
    }
    __syncthreads();

    constexpr float E[14] = {
        Ecoef(-6), Ecoef(-5), Ecoef(-4), Ecoef(-3), Ecoef(-2), Ecoef(-1),
        Ecoef(0),  Ecoef(1),  Ecoef(2),  Ecoef(3),  Ecoef(4),  Ecoef(5),
        Ecoef(6),  Ecoef(7) };
    constexpr float O[14] = {
        Ocoef(-6), Ocoef(-5), Ocoef(-4), Ocoef(-3), Ocoef(-2), Ocoef(-1),
        Ocoef(0),  Ocoef(1),  Ocoef(2),  Ocoef(3),  Ocoef(4),  Ocoef(5),
        Ocoef(6),  Ocoef(7) };

    float* __restrict__ lo = low + row * (size_t)ROW_L;
    float* __restrict__ hi = high + row * (size_t)ROW_L;

#pragma unroll
    for (int ii = 0; ii < 4; ii++) {
        const int i = t + ii * 256;    // float4 output index; outputs n = 4i..4i+3

        // window: w[c] = sx[4i + c] = x_sym[4i + c - 8], c = 0..19
        // 5 aligned float4 LDS, lane stride 16B -> conflict-free
        float w[20];
#pragma unroll
        for (int b = 0; b < 5; b++) {
            float4 v = s4[i + b];
            w[4 * b + 0] = v.x; w[4 * b + 1] = v.y;
            w[4 * b + 2] = v.z; w[4 * b + 3] = v.w;
        }

        // n=4i   (even, 2q=4i):   taps w[d+8],  d=-6..7 -> w[2..15]
        // n=4i+1 (odd,  2q=4i):   taps w[d+8]
        // n=4i+2 (even, 2q=4i+2): taps w[d+10] -> w[4..17]
        // n=4i+3 (odd,  2q=4i+2): taps w[d+10]
        float l0 = 0.f, l1 = 0.f, l2 = 0.f, l3 = 0.f;
#pragma unroll
        for (int d = 0; d < 14; d++) {
            l0 += E[d] * w[d + 2];
            l1 += O[d] * w[d + 2];
            l2 += E[d] * w[d + 4];
            l3 += O[d] * w[d + 4];
        }

        // x[4i + r] = x_sym[4i + r] = w[r + 8]
        ((float4*)lo)[i] = make_float4(l0, l1, l2, l3);
        ((float4*)hi)[i] = make_float4(w[8] - l0, w[9] - l1,
                                       w[10] - l2, w[11] - l3);
    }
}

extern "C" void kernel_launch(void* const* d_in, const int* in_sizes, int n_in,
                              void* d_out, int out_size)
{
    const float* x = (const float*)d_in[0];
    const int n = in_sizes[0];              // B*C*L
    const int rows = n / ROW_L;             // 8192
    float* low = (float*)d_out;             // tuple order: (low_freq, high_freq)
    float* high = (float*)d_out + (size_t)n;

    db4_fused_kernel<<<rows, 256>>>(x, low, high);
}

// round 8
// speedup vs baseline: 1.1032x; 1.0141x over previous
#include <cuda_runtime.h>

// db4 dec_lo coefficients
static constexpr float Gf[8] = {
    -0.010597401784997278f,  0.032883011666982945f,
     0.030841381835986965f, -0.18703481171888114f,
    -0.02798376941698385f,   0.6308807679295904f,
     0.7148465705525415f,    0.23037781330885523f };

// Composed analysis+synthesis filters (details zeroed):
//   low[2q]   = sum_{d=-6..7} Ecoef(d) * x_sym[2q+d]
//   low[2q+1] = sum_{d=-6..7} Ocoef(d) * x_sym[2q+d]
__host__ __device__ static constexpr float Ecoef(int d) {
    float r = 0.f;
    for (int j = 0; j < 4; j++) {
        int s = 2 * j + 1 - d;
        if (s >= 0 && s < 8) r += Gf[2 * j + 1] * Gf[s];
    }
    return r;
}
__host__ __device__ static constexpr float Ocoef(int d) {
    float r = 0.f;
    for (int j = 0; j < 4; j++) {
        int s = 2 * j + 1 - d;
        if (s >= 0 && s < 8) r += Gf[2 * j] * Gf[s];
    }
    return r;
}

#define ROW_L 4096

// sx[m] = x_sym[m - 8], m in [0, 4112): symmetric extension baked into halo.
__global__ __launch_bounds__(256) void db4_fused_kernel(
    const float* __restrict__ x,
    float* __restrict__ low,
    float* __restrict__ high)
{
    __shared__ float sx[ROW_L + 16];   // 4112 floats = 16.4 KB

    const int t = threadIdx.x;
    const size_t row = blockIdx.x;
    const float* __restrict__ xr = x + row * (size_t)ROW_L;

    // --- Phase 1: load row (float4, coalesced) into regs + shared, plus halos.
    const float4* __restrict__ x4 = (const float4*)xr;
    float4* s4 = (float4*)sx;

    float4 own[4];
#pragma unroll
    for (int ii = 0; ii < 4; ii++) {
        own[ii] = __ldcs(&x4[t + ii * 256]);
    }
    float halo = 0.f;
    if (t < 16) {
        // t in [0,8):  sx[t]        = x[7 - t]      (left symmetric ext)
        // t in [8,16): sx[4104+t-8] = x[4095-(t-8)] (right symmetric ext)
        halo = (t < 8) ? __ldcs(&xr[7 - t]) : __ldcs(&xr[4103 - t]);
    }
#pragma unroll
    for (int ii = 0; ii < 4; ii++) {
        s4[t + ii * 256 + 2] = own[ii];   // sx[m]=x[m-8] for m=8..4103
    }
    if (t < 16) {
        int dst = (t < 8) ? t : (4096 + t);   // 4104 + (t-8)
        sx[dst] = halo;
    }
    __syncthreads();

    constexpr float E[14] = {
        Ecoef(-6), Ecoef(-5), Ecoef(-4), Ecoef(-3), Ecoef(-2), Ecoef(-1),
        Ecoef(0),  Ecoef(1),  Ecoef(2),  Ecoef(3),  Ecoef(4),  Ecoef(5),
        Ecoef(6),  Ecoef(7) };
    constexpr float O[14] = {
        Ocoef(-6), Ocoef(-5), Ocoef(-4), Ocoef(-3), Ocoef(-2), Ocoef(-1),
        Ocoef(0),  Ocoef(1),  Ocoef(2),  Ocoef(3),  Ocoef(4),  Ocoef(5),
        Ocoef(6),  Ocoef(7) };

    float* __restrict__ lo = low + row * (size_t)ROW_L;
    float* __restrict__ hi = high + row * (size_t)ROW_L;

#pragma unroll
    for (int ii = 0; ii < 4; ii++) {
        const int i = t + ii * 256;    // float4 output index; outputs n = 4i..4i+3

        // window: w[c] = sx[4i + c], c = 0..19
        // own float4 supplies w[8..11] (s4[i+2]); 4 conflict-free float4 LDS
        float w[20];
        float4 v0 = s4[i];
        float4 v1 = s4[i + 1];
        float4 v3 = s4[i + 3];
        float4 v4 = s4[i + 4];
        w[0]=v0.x; w[1]=v0.y; w[2]=v0.z;  w[3]=v0.w;
        w[4]=v1.x; w[5]=v1.y; w[6]=v1.z;  w[7]=v1.w;
        w[8]=own[ii].x; w[9]=own[ii].y; w[10]=own[ii].z; w[11]=own[ii].w;
        w[12]=v3.x; w[13]=v3.y; w[14]=v3.z; w[15]=v3.w;
        w[16]=v4.x; w[17]=v4.y; w[18]=v4.z; w[19]=v4.w;

        float l0 = 0.f, l1 = 0.f, l2 = 0.f, l3 = 0.f;
#pragma unroll
        for (int d = 0; d < 14; d++) {
            l0 += E[d] * w[d + 2];
            l1 += O[d] * w[d + 2];
            l2 += E[d] * w[d + 4];
            l3 += O[d] * w[d + 4];
        }

        __stcs(&((float4*)lo)[i], make_float4(l0, l1, l2, l3));
        __stcs(&((float4*)hi)[i], make_float4(own[ii].x - l0, own[ii].y - l1,
                                              own[ii].z - l2, own[ii].w - l3));
    }
}

extern "C" void kernel_launch(void* const* d_in, const int* in_sizes, int n_in,
                              void* d_out, int out_size)
{
    const float* x = (const float*)d_in[0];
    const int n = in_sizes[0];              // B*C*L
    const int rows = n / ROW_L;             // 8192
    float* low = (float*)d_out;             // tuple order: (low_freq, high_freq)
    float* high = (float*)d_out + (size_t)n;

    db4_fused_kernel<<<rows, 256>>>(x, low, high);
}